// round 16
// baseline (speedup 1.0000x reference)
#include <cuda_runtime.h>
#include <cuda_bf16.h>
#include <stdint.h>
#include <stddef.h>

#define BDIM 64
#define SDIM 512
#define IDIM 1024
#define HDIM 1024
#define GDIM 4096            // 4*H
#define MROWS (BDIM*SDIM)    // 32768
#define NCTA 128

// ---------------- static device scratch (no allocations allowed) ----------------
__device__ float          g_xW [(size_t)MROWS * GDIM];   // 512 MB: x@W + bias
__device__ __nv_bfloat16  g_xhi[(size_t)MROWS * IDIM];
__device__ __nv_bfloat16  g_xlo[(size_t)MROWS * IDIM];
__device__ __nv_bfloat16  g_Whi[(size_t)IDIM * GDIM];    // TRANSPOSED: Wt[n][k]
__device__ __nv_bfloat16  g_Wlo[(size_t)IDIM * GDIM];    // TRANSPOSED: Wt[n][k]
__device__ __nv_bfloat16  g_Uhi[(size_t)HDIM * GDIM];
__device__ __nv_bfloat16  g_Ulo[(size_t)HDIM * GDIM];
__device__ __nv_bfloat16  g_hbuf[2][2][BDIM * HDIM];     // [parity][hi/lo]
__device__ unsigned       g_bars[16][32];                // distributed barrier (128B apart)

// ---------------- helpers ----------------
#define MMA_BF16(Cr, Ar, Br)                                                    \
  asm volatile("mma.sync.aligned.m16n8k16.row.col.f32.bf16.bf16.f32 "           \
               "{%0,%1,%2,%3},{%4,%5,%6,%7},{%8,%9},{%0,%1,%2,%3};"             \
               : "+f"(Cr[0]), "+f"(Cr[1]), "+f"(Cr[2]), "+f"(Cr[3])             \
               : "r"(Ar[0]), "r"(Ar[1]), "r"(Ar[2]), "r"(Ar[3]),                \
                 "r"(Br[0]), "r"(Br[1]))

__device__ __forceinline__ void ldsm4(uint32_t* r, uint32_t addr) {
    asm volatile("ldmatrix.sync.aligned.m8n8.x4.shared.b16 {%0,%1,%2,%3}, [%4];"
                 : "=r"(r[0]), "=r"(r[1]), "=r"(r[2]), "=r"(r[3]) : "r"(addr));
}
__device__ __forceinline__ void cpasync16(uint32_t dst, const void* src) {
    asm volatile("cp.async.cg.shared.global [%0], [%1], 16;" :: "r"(dst), "l"(src) : "memory");
}
#define CP_COMMIT()  asm volatile("cp.async.commit_group;" ::: "memory")
#define CP_WAIT1()   asm volatile("cp.async.wait_group 1;" ::: "memory")
#define CP_WAIT0()   asm volatile("cp.async.wait_group 0;" ::: "memory")
#define PAIR_BAR(id) asm volatile("bar.sync %0, 64;" :: "r"(id) : "memory")

__device__ __forceinline__ float sigm(float x) { return 1.f / (1.f + __expf(-x)); }
__device__ __forceinline__ float tanh_f(float x) {
    float e = __expf(-2.f * fabsf(x));
    float r = (1.f - e) / (1.f + e);
    return (x < 0.f) ? -r : r;
}

// ---------------- prep: fp32 -> bf16 hi/lo split (single merged kernel) ------
#define NX (MROWS * IDIM)          // 33554432
#define NW (IDIM * GDIM)           // 4194304
__global__ void split_all_kernel(const float* __restrict__ x,
                                 const float* __restrict__ W,
                                 const float* __restrict__ U) {
    int i = blockIdx.x * blockDim.x + threadIdx.x;
    if (i < NX) {
        float v = x[i];
        __nv_bfloat16 h = __float2bfloat16(v);
        g_xhi[i] = h;
        g_xlo[i] = __float2bfloat16(v - __bfloat162float(h));
    } else if (i < NX + NW) {
        int idx = i - NX;                      // idx = k*4096 + n
        int k = idx >> 12, n = idx & 4095;
        float v = W[idx];
        __nv_bfloat16 h = __float2bfloat16(v);
        size_t d = (size_t)n * IDIM + k;       // transposed
        g_Whi[d] = h;
        g_Wlo[d] = __float2bfloat16(v - __bfloat162float(h));
    } else if (i < NX + 2 * NW) {
        int idx = i - NX - NW;
        float v = U[idx];
        __nv_bfloat16 h = __float2bfloat16(v);
        g_Uhi[idx] = h;
        g_Ulo[idx] = __float2bfloat16(v - __bfloat162float(h));
    }
}

__global__ void zero_state_kernel() {
    int i = blockIdx.x * blockDim.x + threadIdx.x;
    if (i < 16) g_bars[i][0] = 0;
    if (i < BDIM * HDIM) {
        __nv_bfloat16 z = __float2bfloat16(0.f);
        g_hbuf[0][0][i] = z; g_hbuf[0][1][i] = z;
        g_hbuf[1][0][i] = z; g_hbuf[1][1][i] = z;
    }
}

// ---------------- phase 1: xW = x @ W + bias  (bf16x3, cp.async 3-stage) -----
// BYTE-IDENTICAL to R15: 256 threads, 128x128 tile, BK=16, 2 CTAs/SM.
#define P1_NS 3
#define P1_AS_ELEMS (P1_NS * 2 * 128 * 24)
#define P1_AS(s, hl, r, k)  ((((s)*2 + (hl))*128 + (r))*24 + (k))
#define P1_BS(s, hl, n, k)  (P1_AS_ELEMS + (((s)*2 + (hl))*128 + (n))*24 + (k))
#define SMEM1_DYN ((P1_AS_ELEMS + P1_NS * 2 * 128 * 24) * 2)

__global__ __launch_bounds__(256, 2) void gemm_xw_kernel(const float* __restrict__ bias) {
    const int m0 = blockIdx.y * 128;
    const int n0 = blockIdx.x * 128;
    const int tid = threadIdx.x;
    const int warp = tid >> 5, lane = tid & 31;
    const int g = lane >> 2, tig = lane & 3;
    const int wm = warp >> 2, wn = warp & 3;   // 2 x 4 warp grid

    extern __shared__ __align__(16) char smem_raw[];
    __nv_bfloat16* S = reinterpret_cast<__nv_bfloat16*>(smem_raw);
    const uint32_t s_base = (uint32_t)__cvta_generic_to_shared(S);

    float C[4][4][4];
#pragma unroll
    for (int a = 0; a < 4; a++)
#pragma unroll
        for (int b = 0; b < 4; b++)
#pragma unroll
            for (int c = 0; c < 4; c++) C[a][b][c] = 0.f;

    const int la_row  = lane & 15;
    const int la_koff = (lane >> 4) * 8;
    const int lb_col  = (lane & 7) + ((lane >> 4) << 3);
    const int lb_koff = ((lane >> 3) & 1) * 8;

    auto stage_load = [&](int s, int k0) {
#pragma unroll
        for (int c = 0; c < 2; ++c) {
            int cc = c * 256 + tid;
            int hl = cc >> 8, rem = cc & 255;
            int row = rem >> 1, col = (rem & 1) * 8;
            const __nv_bfloat16* src = (hl ? g_xlo : g_xhi) + (size_t)(m0 + row) * IDIM + k0 + col;
            cpasync16(s_base + (uint32_t)P1_AS(s, hl, row, col) * 2, src);
        }
#pragma unroll
        for (int c = 0; c < 2; ++c) {
            int cc = c * 256 + tid;
            int hl = cc >> 8, rem = cc & 255;
            int row = rem >> 1, col = (rem & 1) * 8;
            const __nv_bfloat16* src = (hl ? g_Wlo : g_Whi) + (size_t)(n0 + row) * IDIM + k0 + col;
            cpasync16(s_base + (uint32_t)P1_BS(s, hl, row, col) * 2, src);
        }
        CP_COMMIT();
    };

    stage_load(0, 0);
    stage_load(1, 16);

    const int KT = IDIM / 16;
    for (int kt = 0; kt < KT; ++kt) {
        if (kt + 2 < KT) CP_WAIT1(); else CP_WAIT0();
        __syncthreads();
        if (kt + 2 < KT) stage_load((kt + 2) % P1_NS, (kt + 2) * 16);

        const int cur = kt % P1_NS;
        uint32_t aF[2][4][4];
        uint32_t bF[2][4][2];
#pragma unroll
        for (int mt = 0; mt < 4; ++mt)
#pragma unroll
            for (int h = 0; h < 2; ++h)
                ldsm4(aF[h][mt],
                      s_base + (uint32_t)P1_AS(cur, h, wm * 64 + mt * 16 + la_row, la_koff) * 2);
#pragma unroll
        for (int h = 0; h < 2; ++h)
#pragma unroll
            for (int a = 0; a < 4; a += 2)
                ldsm4(&bF[h][a][0],
                      s_base + (uint32_t)P1_BS(cur, h, wn * 32 + a * 8 + lb_col, lb_koff) * 2);
#pragma unroll
        for (int mt = 0; mt < 4; ++mt)
#pragma unroll
            for (int nt = 0; nt < 4; ++nt) {
                MMA_BF16(C[mt][nt], aF[0][mt], bF[0][nt]);  // hi*hi
                MMA_BF16(C[mt][nt], aF[0][mt], bF[1][nt]);  // hi*lo
                MMA_BF16(C[mt][nt], aF[1][mt], bF[0][nt]);  // lo*hi
            }
        __syncthreads();
    }

#pragma unroll
    for (int mt = 0; mt < 4; ++mt) {
        const int row0 = m0 + wm * 64 + mt * 16 + g;
#pragma unroll
        for (int nt = 0; nt < 4; ++nt) {
            const int col = n0 + wn * 32 + nt * 8 + 2 * tig;
            const float b0 = bias[col], b1 = bias[col + 1];
            float2 v;
            v.x = C[mt][nt][0] + b0; v.y = C[mt][nt][1] + b1;
            *reinterpret_cast<float2*>(&g_xW[(size_t)row0 * GDIM + col]) = v;
            v.x = C[mt][nt][2] + b0; v.y = C[mt][nt][3] + b1;
            *reinterpret_cast<float2*>(&g_xW[(size_t)(row0 + 8) * GDIM + col]) = v;
        }
    }
}

// ---------------- phase 2: persistent recurrent kernel ----------------------
// R15 structure, ONE change: 3 independent accumulator sets (one per bf16x3
// term) instead of a single serially-chained C — 3x MMA dependency ILP.
// Merged (plus xW) only at reduction time.
#define US_PAD    1032
#define US_BYTES  (2 * 32 * US_PAD * 2)
#define AS2_ST    72
#define ASI2(buf, hl, hf, r, k) ((((((buf)*2 + (hl))*2 + (hf))*64 + (r))*AS2_ST) + (k))
#define AS2_BYTES (2*2*2*64*AS2_ST*2)
#define SMEM2_DYN (US_BYTES + AS2_BYTES)
#define USI(hl, n, k)  (((hl) * 32 + (n)) * US_PAD + (k))

__global__ __launch_bounds__(512) void lstm_persistent_kernel(float* __restrict__ out,
                                                              float* __restrict__ ht,
                                                              float* __restrict__ ct) {
    const int j0 = blockIdx.x * 8;
    const int tid = threadIdx.x;
    const int warp = tid >> 5, lane = tid & 31;
    const int g = lane >> 2, tig = lane & 3;
    const int wb   = warp & 3;             // batch group (rows wb*16..+15)
    const int half = (warp >> 2) & 1;      // K-half
    const int nh   = warp >> 3;            // N-half (0: gates i,f ; 1: gates g,o)
    const int pair_id = 1 + half * 4 + wb; // named barrier id (1..8)
    const int pl   = nh * 32 + lane;       // lane within the 64-thread pair

    extern __shared__ __align__(16) char smem_raw[];
    __nv_bfloat16* Us = reinterpret_cast<__nv_bfloat16*>(smem_raw);
    __nv_bfloat16* As = reinterpret_cast<__nv_bfloat16*>(smem_raw + US_BYTES);
    float* red  = reinterpret_cast<float*>(smem_raw + US_BYTES);   // reuse of As
    float* red2 = red + 2048;                                      // gate g,o hand-off
    const uint32_t us_base = (uint32_t)__cvta_generic_to_shared(Us);
    const uint32_t as_base = (uint32_t)__cvta_generic_to_shared(As);

    // ---- one-time: load this CTA's U slice into SMEM ----
#pragma unroll
    for (int hl = 0; hl < 2; ++hl) {
        const __nv_bfloat16* Ug = hl ? g_Ulo : g_Uhi;
        for (int i = tid; i < 4096; i += 512) {
            int k = i >> 2, grp = i & 3;
            uint4 v = *reinterpret_cast<const uint4*>(Ug + (size_t)k * GDIM + grp * 1024 + j0);
            __nv_bfloat16 tmp[8];
            *reinterpret_cast<uint4*>(tmp) = v;
#pragma unroll
            for (int c = 0; c < 8; ++c) Us[USI(hl, grp * 8 + c, k)] = tmp[c];
        }
    }
    __syncthreads();

    // ldmatrix lane maps
    const int la_row  = wb * 16 + (lane & 15);
    const int la_koff = (lane >> 4) * 8;
    const int lu_col  = nh * 16 + (lane & 7) + ((lane >> 4) << 3);
    const int lu_koff = ((lane >> 3) & 1) * 8;

    float creg[4] = {0.f, 0.f, 0.f, 0.f};   // persistent c state (warps half0/nh0)
    float2 pv0[2], pv1[2];                  // prefetched xW (this warp's 2 gates)

    auto prefetch_xw = [&](int tt) {
        if (half == 0 && tt < SDIM) {
            const int b0 = wb * 16 + g;
#pragma unroll
            for (int nt = 0; nt < 2; ++nt) {
                const int n = (nh * 2 + nt) * 1024 + j0 + 2 * tig;
                pv0[nt] = *reinterpret_cast<const float2*>(&g_xW[(size_t)(b0 * SDIM + tt) * GDIM + n]);
                pv1[nt] = *reinterpret_cast<const float2*>(&g_xW[(size_t)((b0 + 8) * SDIM + tt) * GDIM + n]);
            }
        }
    };
    prefetch_xw(0);

    for (int t = 0; t < SDIM; ++t) {
        const int p = t & 1, np = p ^ 1;
        const __nv_bfloat16* __restrict__ hhi = g_hbuf[p][0];
        const __nv_bfloat16* __restrict__ hlo = g_hbuf[p][1];

        // 3 independent accumulator sets, one per bf16x3 term (MMA ILP)
        float C3[3][2][4];
#pragma unroll
        for (int s = 0; s < 3; ++s)
#pragma unroll
            for (int nt = 0; nt < 2; ++nt)
#pragma unroll
                for (int c = 0; c < 4; ++c) C3[s][nt][c] = 0.f;

        // cp.async pair staging of h chunk ch (64 K of this pair's half)
        auto stage = [&](int ch) {
            const int buf = ch & 1;
#pragma unroll
            for (int c = 0; c < 4; ++c) {
                int idx = c * 64 + pl;
                int hl = idx >> 7, rem = idx & 127;
                int row16 = rem >> 3, kseg = (rem & 7) * 8;
                const __nv_bfloat16* src = (hl ? hlo : hhi)
                    + (size_t)(wb * 16 + row16) * HDIM + half * 512 + ch * 64 + kseg;
                cpasync16(as_base + (uint32_t)ASI2(buf, hl, half, wb * 16 + row16, kseg) * 2, src);
            }
            CP_COMMIT();
        };

        stage(0);
        stage(1);

        const int NCH = 8;   // 512 K per half / 64
        for (int ch = 0; ch < NCH; ++ch) {
            if (ch < NCH - 1) CP_WAIT1(); else CP_WAIT0();
            PAIR_BAR(pair_id);                 // chunk ch visible to both warps of pair

            const int cur = ch & 1;
#pragma unroll
            for (int k16 = 0; k16 < 4; ++k16) {
                const int kkl = k16 * 16;
                const int kk = half * 512 + ch * 64 + kkl;   // global K for U
                uint32_t aF[2][4];
                uint32_t bF[2][4];
#pragma unroll
                for (int hl = 0; hl < 2; ++hl)
                    ldsm4(aF[hl], as_base + (uint32_t)ASI2(cur, hl, half, la_row, kkl + la_koff) * 2);
#pragma unroll
                for (int hl = 0; hl < 2; ++hl)
                    ldsm4(bF[hl], us_base + (uint32_t)USI(hl, lu_col, kk + lu_koff) * 2);
#pragma unroll
                for (int nt = 0; nt < 2; ++nt) {
                    MMA_BF16(C3[0][nt], aF[0], (bF[0] + nt * 2));   // hi*hi
                    MMA_BF16(C3[1][nt], aF[0], (bF[1] + nt * 2));   // hi*lo(U)
                    MMA_BF16(C3[2][nt], aF[1], (bF[0] + nt * 2));   // lo(h)*hi
                }
            }

            PAIR_BAR(pair_id);                 // both warps done reading buf before refill
            if (ch + 2 < NCH) stage(ch + 2);
        }

        // merge the 3 term-sets (+ xW for half0)
        float C[2][4];
#pragma unroll
        for (int nt = 0; nt < 2; ++nt)
#pragma unroll
            for (int c = 0; c < 4; ++c)
                C[nt][c] = C3[0][nt][c] + C3[1][nt][c] + C3[2][nt][c];
        if (half == 0) {
#pragma unroll
            for (int nt = 0; nt < 2; ++nt) {
                C[nt][0] += pv0[nt].x; C[nt][1] += pv0[nt].y;
                C[nt][2] += pv1[nt].x; C[nt][3] += pv1[nt].y;
            }
        }

        // red/red2 alias As: make sure every pair is done with its As reads
        __syncthreads();

        // ---- stage 1: K-half merge (half1 -> half0) ----
        if (half == 1) {
            float* dst = &red[(((nh * 4 + wb) * 32) + lane) * 8];
#pragma unroll
            for (int nt = 0; nt < 2; ++nt)
#pragma unroll
                for (int c = 0; c < 4; ++c) dst[nt * 4 + c] = C[nt][c];
        }
        __syncthreads();
        if (half == 0) {
            const float* src = &red[(((nh * 4 + wb) * 32) + lane) * 8];
#pragma unroll
            for (int nt = 0; nt < 2; ++nt)
#pragma unroll
                for (int c = 0; c < 4; ++c) C[nt][c] += src[nt * 4 + c];
        }

        // ---- stage 2: gates {g,o} hand-off (half0/nh1 -> half0/nh0) ----
        if (half == 0 && nh == 1) {
            float* dst = &red2[((wb * 32) + lane) * 8];
#pragma unroll
            for (int nt = 0; nt < 2; ++nt)
#pragma unroll
                for (int c = 0; c < 4; ++c) dst[nt * 4 + c] = C[nt][c];
        }
        __syncthreads();

        if (half == 0 && nh == 0) {
            const float* src = &red2[((wb * 32) + lane) * 8];
            // ---- fused LSTM cell epilogue ----
#pragma unroll
            for (int ci = 0; ci < 4; ++ci) {
                const int b = wb * 16 + g + ((ci & 2) ? 8 : 0);
                const int j = j0 + 2 * tig + (ci & 1);
                const float is = sigm(C[0][ci]);            // gate 0: i
                const float fs = sigm(C[1][ci]);            // gate 1: f
                const float gt = tanh_f(src[0 * 4 + ci]);   // gate 2: g
                const float os = sigm(src[1 * 4 + ci]);     // gate 3: o
                const float cnew = fs * creg[ci] + is * gt;
                creg[ci] = cnew;
                const float h = os * tanh_f(cnew);
                out[(size_t)(b * SDIM + t) * HDIM + j] = h;
                __nv_bfloat16 hh = __float2bfloat16(h);
                g_hbuf[np][0][b * HDIM + j] = hh;
                g_hbuf[np][1][b * HDIM + j] = __float2bfloat16(h - __bfloat162float(hh));
                if (ht != nullptr && t == SDIM - 1) {
                    ht[b * HDIM + j] = h;
                    ct[b * HDIM + j] = cnew;
                }
            }
        }

        // prefetch next step's xW before waiting (independent of barrier)
        prefetch_xw(t + 1);

        // ---- grid-wide barrier: 16 counters, parallel poll by warp 0 ----
        __syncthreads();   // all h stores issued
        if (warp == 0) {
            const unsigned target = (unsigned)(t + 1) * 8u;   // 8 CTAs per counter
            if (lane == 0)
                asm volatile("red.release.gpu.global.add.u32 [%0], %1;"
                             :: "l"(&g_bars[blockIdx.x & 15][0]), "r"(1u) : "memory");
            const int idx = lane & 15;
            unsigned v;
            do {
                asm volatile("ld.acquire.gpu.global.u32 %0, [%1];"
                             : "=r"(v) : "l"(&g_bars[idx][0]) : "memory");
            } while (__any_sync(0xffffffffu, v < target));
        }
        __syncthreads();
    }
}

// ---------------- launch ----------------
// Launch order: split_all(0), gemm(1), zero_state(2), persistent(3) — the ncu
// capture (`-s 5 -c 1`, harness offset 2) lands on the persistent kernel.
extern "C" void kernel_launch(void* const* d_in, const int* in_sizes, int n_in,
                              void* d_out, int out_size) {
    const float* x    = (const float*)d_in[0];
    const float* W    = (const float*)d_in[1];
    const float* U    = (const float*)d_in[2];
    const float* bias = (const float*)d_in[3];
    float* out = (float*)d_out;
    (void)in_sizes; (void)n_in;

    static int smem_set = 0;
    if (!smem_set) {
        cudaFuncSetAttribute(lstm_persistent_kernel,
                             cudaFuncAttributeMaxDynamicSharedMemorySize, SMEM2_DYN);
        cudaFuncSetAttribute(gemm_xw_kernel,
                             cudaFuncAttributeMaxDynamicSharedMemorySize, SMEM1_DYN);
        smem_set = 1;
    }

    {
        int n = NX + 2 * NW;
        split_all_kernel<<<(n + 255) / 256, 256>>>(x, W, U);
    }

    gemm_xw_kernel<<<dim3(GDIM / 128, MROWS / 128), 256, SMEM1_DYN>>>(bias);

    zero_state_kernel<<<(BDIM * HDIM + 255) / 256, 256>>>();

    float* ht = nullptr;
    float* ct = nullptr;
    long long hs_elems = (long long)BDIM * SDIM * HDIM;
    if ((long long)out_size >= hs_elems + 2LL * BDIM * HDIM) {
        ht = out + hs_elems;
        ct = ht + (long long)BDIM * HDIM;
    }

    lstm_persistent_kernel<<<NCTA, 512, SMEM2_DYN>>>(out, ht, ct);
}

// round 17
// speedup vs baseline: 1.0543x; 1.0543x over previous
#include <cuda_runtime.h>
#include <cuda_bf16.h>
#include <stdint.h>
#include <stddef.h>

#define BDIM 64
#define SDIM 512
#define IDIM 1024
#define HDIM 1024
#define GDIM 4096            // 4*H
#define MROWS (BDIM*SDIM)    // 32768
#define NCTA 128

// ---------------- static device scratch (no allocations allowed) ----------------
__device__ float          g_xW [(size_t)MROWS * GDIM];   // 512 MB: x@W + bias
__device__ __nv_bfloat16  g_xhi[(size_t)MROWS * IDIM];
__device__ __nv_bfloat16  g_xlo[(size_t)MROWS * IDIM];
__device__ __nv_bfloat16  g_Whi[(size_t)IDIM * GDIM];    // TRANSPOSED: Wt[n][k]
__device__ __nv_bfloat16  g_Wlo[(size_t)IDIM * GDIM];    // TRANSPOSED: Wt[n][k]
__device__ __nv_bfloat16  g_Uhi[(size_t)HDIM * GDIM];
__device__ __nv_bfloat16  g_Ulo[(size_t)HDIM * GDIM];
__device__ __nv_bfloat16  g_hbuf[2][2][BDIM * HDIM];     // [parity][hi/lo]
__device__ unsigned       g_bars[16][32];                // distributed barrier (128B apart)

// ---------------- helpers ----------------
#define MMA_BF16(Cr, Ar, Br)                                                    \
  asm volatile("mma.sync.aligned.m16n8k16.row.col.f32.bf16.bf16.f32 "           \
               "{%0,%1,%2,%3},{%4,%5,%6,%7},{%8,%9},{%0,%1,%2,%3};"             \
               : "+f"(Cr[0]), "+f"(Cr[1]), "+f"(Cr[2]), "+f"(Cr[3])             \
               : "r"(Ar[0]), "r"(Ar[1]), "r"(Ar[2]), "r"(Ar[3]),                \
                 "r"(Br[0]), "r"(Br[1]))

__device__ __forceinline__ void ldsm4(uint32_t* r, uint32_t addr) {
    asm volatile("ldmatrix.sync.aligned.m8n8.x4.shared.b16 {%0,%1,%2,%3}, [%4];"
                 : "=r"(r[0]), "=r"(r[1]), "=r"(r[2]), "=r"(r[3]) : "r"(addr));
}
__device__ __forceinline__ void cpasync16(uint32_t dst, const void* src) {
    asm volatile("cp.async.cg.shared.global [%0], [%1], 16;" :: "r"(dst), "l"(src) : "memory");
}
#define CP_COMMIT()  asm volatile("cp.async.commit_group;" ::: "memory")
#define CP_WAIT1()   asm volatile("cp.async.wait_group 1;" ::: "memory")
#define CP_WAIT0()   asm volatile("cp.async.wait_group 0;" ::: "memory")
#define PAIR_BAR(id) asm volatile("bar.sync %0, 64;" :: "r"(id) : "memory")

__device__ __forceinline__ float sigm(float x) { return 1.f / (1.f + __expf(-x)); }
__device__ __forceinline__ float tanh_f(float x) {
    float e = __expf(-2.f * fabsf(x));
    float r = (1.f - e) / (1.f + e);
    return (x < 0.f) ? -r : r;
}

// ---------------- prep: fp32 -> bf16 hi/lo split (single merged kernel) ------
#define NX (MROWS * IDIM)          // 33554432
#define NW (IDIM * GDIM)           // 4194304
__global__ void split_all_kernel(const float* __restrict__ x,
                                 const float* __restrict__ W,
                                 const float* __restrict__ U) {
    int i = blockIdx.x * blockDim.x + threadIdx.x;
    if (i < NX) {
        float v = x[i];
        __nv_bfloat16 h = __float2bfloat16(v);
        g_xhi[i] = h;
        g_xlo[i] = __float2bfloat16(v - __bfloat162float(h));
    } else if (i < NX + NW) {
        int idx = i - NX;                      // idx = k*4096 + n
        int k = idx >> 12, n = idx & 4095;
        float v = W[idx];
        __nv_bfloat16 h = __float2bfloat16(v);
        size_t d = (size_t)n * IDIM + k;       // transposed
        g_Whi[d] = h;
        g_Wlo[d] = __float2bfloat16(v - __bfloat162float(h));
    } else if (i < NX + 2 * NW) {
        int idx = i - NX - NW;
        float v = U[idx];
        __nv_bfloat16 h = __float2bfloat16(v);
        g_Uhi[idx] = h;
        g_Ulo[idx] = __float2bfloat16(v - __bfloat162float(h));
    }
}

__global__ void zero_state_kernel() {
    int i = blockIdx.x * blockDim.x + threadIdx.x;
    if (i < 16) g_bars[i][0] = 0;
    if (i < BDIM * HDIM) {
        __nv_bfloat16 z = __float2bfloat16(0.f);
        g_hbuf[0][0][i] = z; g_hbuf[0][1][i] = z;
        g_hbuf[1][0][i] = z; g_hbuf[1][1][i] = z;
    }
}

// ---------------- phase 1: xW = x @ W + bias  (bf16x3, cp.async) -------------
// 256 threads, CTA tile 128x128, BK=32, 2-stage double buffer, 2 CTAs/SM.
// Halved sync count vs BK=16; doubled cp.async MLP per commit group.
// K iteration order identical to R15 -> bitwise-identical xW.
#define P1_ST 40                 // 32 K + 8 pad
#define P1_AS(s, hl, r, k)  ((((s)*2 + (hl))*128 + (r))*P1_ST + (k))
#define P1_AS_ELEMS (2 * 2 * 128 * P1_ST)
#define P1_BS(s, hl, n, k)  (P1_AS_ELEMS + (((s)*2 + (hl))*128 + (n))*P1_ST + (k))
#define SMEM1_DYN ((P1_AS_ELEMS + 2 * 2 * 128 * P1_ST) * 2)

__global__ __launch_bounds__(256, 2) void gemm_xw_kernel(const float* __restrict__ bias) {
    const int m0 = blockIdx.y * 128;
    const int n0 = blockIdx.x * 128;
    const int tid = threadIdx.x;
    const int warp = tid >> 5, lane = tid & 31;
    const int g = lane >> 2, tig = lane & 3;
    const int wm = warp >> 2, wn = warp & 3;   // 2 x 4 warp grid

    extern __shared__ __align__(16) char smem_raw[];
    __nv_bfloat16* S = reinterpret_cast<__nv_bfloat16*>(smem_raw);
    const uint32_t s_base = (uint32_t)__cvta_generic_to_shared(S);

    float C[4][4][4];
#pragma unroll
    for (int a = 0; a < 4; a++)
#pragma unroll
        for (int b = 0; b < 4; b++)
#pragma unroll
            for (int c = 0; c < 4; c++) C[a][b][c] = 0.f;

    const int la_row  = lane & 15;
    const int la_koff = (lane >> 4) * 8;
    const int lb_col  = (lane & 7) + ((lane >> 4) << 3);
    const int lb_koff = ((lane >> 3) & 1) * 8;

    // staging (one 32-K stage): A = 2hl x 128 rows x 4 chunks = 1024 (4/thread)
    //                           B same (4/thread)
    auto stage_load = [&](int s, int k0) {
#pragma unroll
        for (int c = 0; c < 4; ++c) {
            int cc = c * 256 + tid;
            int hl = cc >> 9, rem = cc & 511;
            int row = rem >> 2, col = (rem & 3) * 8;
            const __nv_bfloat16* src = (hl ? g_xlo : g_xhi) + (size_t)(m0 + row) * IDIM + k0 + col;
            cpasync16(s_base + (uint32_t)P1_AS(s, hl, row, col) * 2, src);
        }
#pragma unroll
        for (int c = 0; c < 4; ++c) {
            int cc = c * 256 + tid;
            int hl = cc >> 9, rem = cc & 511;
            int row = rem >> 2, col = (rem & 3) * 8;
            const __nv_bfloat16* src = (hl ? g_Wlo : g_Whi) + (size_t)(n0 + row) * IDIM + k0 + col;
            cpasync16(s_base + (uint32_t)P1_BS(s, hl, row, col) * 2, src);
        }
        CP_COMMIT();
    };

    stage_load(0, 0);
    stage_load(1, 32);

    const int KT = IDIM / 32;   // 32 iterations
    for (int kt = 0; kt < KT; ++kt) {
        if (kt + 1 < KT) CP_WAIT1(); else CP_WAIT0();
        __syncthreads();                       // stage kt landed, visible

        const int cur = kt & 1;
#pragma unroll
        for (int k16 = 0; k16 < 2; ++k16) {
            const int kkl = k16 * 16;
            uint32_t aF[2][4][4];
            uint32_t bF[2][4][2];
#pragma unroll
            for (int mt = 0; mt < 4; ++mt)
#pragma unroll
                for (int h = 0; h < 2; ++h)
                    ldsm4(aF[h][mt],
                          s_base + (uint32_t)P1_AS(cur, h, wm * 64 + mt * 16 + la_row, kkl + la_koff) * 2);
#pragma unroll
            for (int h = 0; h < 2; ++h)
#pragma unroll
                for (int a = 0; a < 4; a += 2)
                    ldsm4(&bF[h][a][0],
                          s_base + (uint32_t)P1_BS(cur, h, wn * 32 + a * 8 + lb_col, kkl + lb_koff) * 2);
#pragma unroll
            for (int mt = 0; mt < 4; ++mt)
#pragma unroll
                for (int nt = 0; nt < 4; ++nt) {
                    MMA_BF16(C[mt][nt], aF[0][mt], bF[0][nt]);  // hi*hi
                    MMA_BF16(C[mt][nt], aF[0][mt], bF[1][nt]);  // hi*lo
                    MMA_BF16(C[mt][nt], aF[1][mt], bF[0][nt]);  // lo*hi
                }
        }

        __syncthreads();                       // all reads of cur done
        if (kt + 2 < KT) stage_load(cur, (kt + 2) * 32);
    }

#pragma unroll
    for (int mt = 0; mt < 4; ++mt) {
        const int row0 = m0 + wm * 64 + mt * 16 + g;
#pragma unroll
        for (int nt = 0; nt < 4; ++nt) {
            const int col = n0 + wn * 32 + nt * 8 + 2 * tig;
            const float b0 = bias[col], b1 = bias[col + 1];
            float2 v;
            v.x = C[mt][nt][0] + b0; v.y = C[mt][nt][1] + b1;
            *reinterpret_cast<float2*>(&g_xW[(size_t)row0 * GDIM + col]) = v;
            v.x = C[mt][nt][2] + b0; v.y = C[mt][nt][3] + b1;
            *reinterpret_cast<float2*>(&g_xW[(size_t)(row0 + 8) * GDIM + col]) = v;
        }
    }
}

// ---------------- phase 2: persistent recurrent kernel ----------------------
// BYTE-IDENTICAL to R15 (proven best): cp.async pair staging, pair barriers,
// two-stage reduction, 16-counter parallel-poll grid barrier. (R16's 3-way
// accumulator split reverted — measured neutral, added alu overhead.)
#define US_PAD    1032
#define US_BYTES  (2 * 32 * US_PAD * 2)
#define AS2_ST    72
#define ASI2(buf, hl, hf, r, k) ((((((buf)*2 + (hl))*2 + (hf))*64 + (r))*AS2_ST) + (k))
#define AS2_BYTES (2*2*2*64*AS2_ST*2)
#define SMEM2_DYN (US_BYTES + AS2_BYTES)
#define USI(hl, n, k)  (((hl) * 32 + (n)) * US_PAD + (k))

__global__ __launch_bounds__(512) void lstm_persistent_kernel(float* __restrict__ out,
                                                              float* __restrict__ ht,
                                                              float* __restrict__ ct) {
    const int j0 = blockIdx.x * 8;
    const int tid = threadIdx.x;
    const int warp = tid >> 5, lane = tid & 31;
    const int g = lane >> 2, tig = lane & 3;
    const int wb   = warp & 3;             // batch group (rows wb*16..+15)
    const int half = (warp >> 2) & 1;      // K-half
    const int nh   = warp >> 3;            // N-half (0: gates i,f ; 1: gates g,o)
    const int pair_id = 1 + half * 4 + wb; // named barrier id (1..8)
    const int pl   = nh * 32 + lane;       // lane within the 64-thread pair

    extern __shared__ __align__(16) char smem_raw[];
    __nv_bfloat16* Us = reinterpret_cast<__nv_bfloat16*>(smem_raw);
    __nv_bfloat16* As = reinterpret_cast<__nv_bfloat16*>(smem_raw + US_BYTES);
    float* red  = reinterpret_cast<float*>(smem_raw + US_BYTES);   // reuse of As
    float* red2 = red + 2048;                                      // gate g,o hand-off
    const uint32_t us_base = (uint32_t)__cvta_generic_to_shared(Us);
    const uint32_t as_base = (uint32_t)__cvta_generic_to_shared(As);

    // ---- one-time: load this CTA's U slice into SMEM ----
#pragma unroll
    for (int hl = 0; hl < 2; ++hl) {
        const __nv_bfloat16* Ug = hl ? g_Ulo : g_Uhi;
        for (int i = tid; i < 4096; i += 512) {
            int k = i >> 2, grp = i & 3;
            uint4 v = *reinterpret_cast<const uint4*>(Ug + (size_t)k * GDIM + grp * 1024 + j0);
            __nv_bfloat16 tmp[8];
            *reinterpret_cast<uint4*>(tmp) = v;
#pragma unroll
            for (int c = 0; c < 8; ++c) Us[USI(hl, grp * 8 + c, k)] = tmp[c];
        }
    }
    __syncthreads();

    // ldmatrix lane maps
    const int la_row  = wb * 16 + (lane & 15);
    const int la_koff = (lane >> 4) * 8;
    const int lu_col  = nh * 16 + (lane & 7) + ((lane >> 4) << 3);
    const int lu_koff = ((lane >> 3) & 1) * 8;

    float creg[4] = {0.f, 0.f, 0.f, 0.f};   // persistent c state (warps half0/nh0)
    float2 pv0[2], pv1[2];                  // prefetched xW (this warp's 2 gates)

    auto prefetch_xw = [&](int tt) {
        if (half == 0 && tt < SDIM) {
            const int b0 = wb * 16 + g;
#pragma unroll
            for (int nt = 0; nt < 2; ++nt) {
                const int n = (nh * 2 + nt) * 1024 + j0 + 2 * tig;
                pv0[nt] = *reinterpret_cast<const float2*>(&g_xW[(size_t)(b0 * SDIM + tt) * GDIM + n]);
                pv1[nt] = *reinterpret_cast<const float2*>(&g_xW[(size_t)((b0 + 8) * SDIM + tt) * GDIM + n]);
            }
        }
    };
    prefetch_xw(0);

    for (int t = 0; t < SDIM; ++t) {
        const int p = t & 1, np = p ^ 1;
        const __nv_bfloat16* __restrict__ hhi = g_hbuf[p][0];
        const __nv_bfloat16* __restrict__ hlo = g_hbuf[p][1];

        float C[2][4];
        if (half == 0) {
#pragma unroll
            for (int nt = 0; nt < 2; ++nt) {
                C[nt][0] = pv0[nt].x; C[nt][1] = pv0[nt].y;
                C[nt][2] = pv1[nt].x; C[nt][3] = pv1[nt].y;
            }
        } else {
#pragma unroll
            for (int nt = 0; nt < 2; ++nt)
#pragma unroll
                for (int c = 0; c < 4; ++c) C[nt][c] = 0.f;
        }

        // cp.async pair staging of h chunk ch (64 K of this pair's half)
        auto stage = [&](int ch) {
            const int buf = ch & 1;
#pragma unroll
            for (int c = 0; c < 4; ++c) {
                int idx = c * 64 + pl;
                int hl = idx >> 7, rem = idx & 127;
                int row16 = rem >> 3, kseg = (rem & 7) * 8;
                const __nv_bfloat16* src = (hl ? hlo : hhi)
                    + (size_t)(wb * 16 + row16) * HDIM + half * 512 + ch * 64 + kseg;
                cpasync16(as_base + (uint32_t)ASI2(buf, hl, half, wb * 16 + row16, kseg) * 2, src);
            }
            CP_COMMIT();
        };

        stage(0);
        stage(1);

        const int NCH = 8;   // 512 K per half / 64
        for (int ch = 0; ch < NCH; ++ch) {
            if (ch < NCH - 1) CP_WAIT1(); else CP_WAIT0();
            PAIR_BAR(pair_id);                 // chunk ch visible to both warps of pair

            const int cur = ch & 1;
#pragma unroll
            for (int k16 = 0; k16 < 4; ++k16) {
                const int kkl = k16 * 16;
                const int kk = half * 512 + ch * 64 + kkl;   // global K for U
                uint32_t aF[2][4];
                uint32_t bF[2][4];
#pragma unroll
                for (int hl = 0; hl < 2; ++hl)
                    ldsm4(aF[hl], as_base + (uint32_t)ASI2(cur, hl, half, la_row, kkl + la_koff) * 2);
#pragma unroll
                for (int hl = 0; hl < 2; ++hl)
                    ldsm4(bF[hl], us_base + (uint32_t)USI(hl, lu_col, kk + lu_koff) * 2);
#pragma unroll
                for (int nt = 0; nt < 2; ++nt) {
                    MMA_BF16(C[nt], aF[0], (bF[0] + nt * 2));   // hi*hi
                    MMA_BF16(C[nt], aF[0], (bF[1] + nt * 2));   // hi*lo(U)
                    MMA_BF16(C[nt], aF[1], (bF[0] + nt * 2));   // lo(h)*hi
                }
            }

            PAIR_BAR(pair_id);                 // both warps done reading buf before refill
            if (ch + 2 < NCH) stage(ch + 2);
        }

        // red/red2 alias As: make sure every pair is done with its As reads
        __syncthreads();

        // ---- stage 1: K-half merge (half1 -> half0) ----
        if (half == 1) {
            float* dst = &red[(((nh * 4 + wb) * 32) + lane) * 8];
#pragma unroll
            for (int nt = 0; nt < 2; ++nt)
#pragma unroll
                for (int c = 0; c < 4; ++c) dst[nt * 4 + c] = C[nt][c];
        }
        __syncthreads();
        if (half == 0) {
            const float* src = &red[(((nh * 4 + wb) * 32) + lane) * 8];
#pragma unroll
            for (int nt = 0; nt < 2; ++nt)
#pragma unroll
                for (int c = 0; c < 4; ++c) C[nt][c] += src[nt * 4 + c];
        }

        // ---- stage 2: gates {g,o} hand-off (half0/nh1 -> half0/nh0) ----
        if (half == 0 && nh == 1) {
            float* dst = &red2[((wb * 32) + lane) * 8];
#pragma unroll
            for (int nt = 0; nt < 2; ++nt)
#pragma unroll
                for (int c = 0; c < 4; ++c) dst[nt * 4 + c] = C[nt][c];
        }
        __syncthreads();

        if (half == 0 && nh == 0) {
            const float* src = &red2[((wb * 32) + lane) * 8];
            // ---- fused LSTM cell epilogue ----
#pragma unroll
            for (int ci = 0; ci < 4; ++ci) {
                const int b = wb * 16 + g + ((ci & 2) ? 8 : 0);
                const int j = j0 + 2 * tig + (ci & 1);
                const float is = sigm(C[0][ci]);            // gate 0: i
                const float fs = sigm(C[1][ci]);            // gate 1: f
                const float gt = tanh_f(src[0 * 4 + ci]);   // gate 2: g
                const float os = sigm(src[1 * 4 + ci]);     // gate 3: o
                const float cnew = fs * creg[ci] + is * gt;
                creg[ci] = cnew;
                const float h = os * tanh_f(cnew);
                out[(size_t)(b * SDIM + t) * HDIM + j] = h;
                __nv_bfloat16 hh = __float2bfloat16(h);
                g_hbuf[np][0][b * HDIM + j] = hh;
                g_hbuf[np][1][b * HDIM + j] = __float2bfloat16(h - __bfloat162float(hh));
                if (ht != nullptr && t == SDIM - 1) {
                    ht[b * HDIM + j] = h;
                    ct[b * HDIM + j] = cnew;
                }
            }
        }

        // prefetch next step's xW before waiting (independent of barrier)
        prefetch_xw(t + 1);

        // ---- grid-wide barrier: 16 counters, parallel poll by warp 0 ----
        __syncthreads();   // all h stores issued
        if (warp == 0) {
            const unsigned target = (unsigned)(t + 1) * 8u;   // 8 CTAs per counter
            if (lane == 0)
                asm volatile("red.release.gpu.global.add.u32 [%0], %1;"
                             :: "l"(&g_bars[blockIdx.x & 15][0]), "r"(1u) : "memory");
            const int idx = lane & 15;
            unsigned v;
            do {
                asm volatile("ld.acquire.gpu.global.u32 %0, [%1];"
                             : "=r"(v) : "l"(&g_bars[idx][0]) : "memory");
            } while (__any_sync(0xffffffffu, v < target));
        }
        __syncthreads();
    }
}

// ---------------- launch ----------------
// Launch order: split_all(0), gemm(1), zero_state(2), persistent(3) — the ncu
// capture (`-s 5 -c 1`, harness offset 2) lands on the persistent kernel.
extern "C" void kernel_launch(void* const* d_in, const int* in_sizes, int n_in,
                              void* d_out, int out_size) {
    const float* x    = (const float*)d_in[0];
    const float* W    = (const float*)d_in[1];
    const float* U    = (const float*)d_in[2];
    const float* bias = (const float*)d_in[3];
    float* out = (float*)d_out;
    (void)in_sizes; (void)n_in;

    static int smem_set = 0;
    if (!smem_set) {
        cudaFuncSetAttribute(lstm_persistent_kernel,
                             cudaFuncAttributeMaxDynamicSharedMemorySize, SMEM2_DYN);
        cudaFuncSetAttribute(gemm_xw_kernel,
                             cudaFuncAttributeMaxDynamicSharedMemorySize, SMEM1_DYN);
        smem_set = 1;
    }

    {
        int n = NX + 2 * NW;
        split_all_kernel<<<(n + 255) / 256, 256>>>(x, W, U);
    }

    gemm_xw_kernel<<<dim3(GDIM / 128, MROWS / 128), 256, SMEM1_DYN>>>(bias);

    zero_state_kernel<<<(BDIM * HDIM + 255) / 256, 256>>>();

    float* ht = nullptr;
    float* ct = nullptr;
    long long hs_elems = (long long)BDIM * SDIM * HDIM;
    if ((long long)out_size >= hs_elems + 2LL * BDIM * HDIM) {
        ht = out + hs_elems;
        ct = ht + (long long)BDIM * HDIM;
    }

    lstm_persistent_kernel<<<NCTA, 512, SMEM2_DYN>>>(out, ht, ct);
}